// round 4
// baseline (speedup 1.0000x reference)
#include <cuda_runtime.h>

typedef unsigned long long u64;

// DeformConv3d: B=2, Cin=32, Cout=64, D=8, H=W=48, 3x3x3, stride1, pad1, dil1.
#define CIN     32
#define COUT    64
#define DDIM    8
#define HDIM    48
#define WDIM    48
#define KTAPS   27
#define POS     64
#define THREADS 256
#define PLANE   (HDIM * WDIM)      // 2304
#define SPATIAL (DDIM * PLANE)     // 18432
#define BATCH   2

#define SVAL_STRIDE 36             // padded row of s_val[pos][.]
#define SWP_STRIDE  260            // padded per-ct block of s_wp (words)

// channels-last copy of x: xT[b][sp][c]
__device__ float g_xT[BATCH * SPATIAL * CIN];
// interleaved weights: g_wp[k][ct][jj][cin][2] = (w[ct*8+2jj][cin], w[ct*8+2jj+1][cin])
__device__ float g_wp[KTAPS * COUT * CIN];

// ---- prep: weight interleave ----
__global__ void prep_w_kernel(const float* __restrict__ w) {
    int i = blockIdx.x * blockDim.x + threadIdx.x;           // over KTAPS*2048
    if (i >= KTAPS * COUT * CIN) return;
    int k  = i / (COUT * CIN);
    int r  = i - k * (COUT * CIN);                           // [ct][jj][cin][2]
    int s  = r & 1;
    int c  = (r >> 1) & 31;
    int jj = (r >> 6) & 3;
    int ct = r >> 8;
    int co = ct * 8 + 2 * jj + s;
    g_wp[i] = w[co * (CIN * KTAPS) + c * KTAPS + k];
}

// ---- prep: x transpose to channels-last ----
__global__ __launch_bounds__(256) void prep_x_kernel(const float* __restrict__ x) {
    __shared__ float s_t[CIN * 65];
    const int t   = threadIdx.x;
    const int blk = blockIdx.x;                  // 576 blocks: (b, sp/64)
    const int b   = blk / (SPATIAL / 64);
    const int sp0 = (blk - b * (SPATIAL / 64)) * 64;
    const float* xb = x + b * (CIN * SPATIAL);
    #pragma unroll
    for (int i = t; i < CIN * 64; i += 256) {    // read: lanes vary sp (coalesced)
        int c = i >> 6, s = i & 63;
        s_t[c * 65 + s] = xb[c * SPATIAL + sp0 + s];
    }
    __syncthreads();
    float* ob = g_xT + (b * SPATIAL + sp0) * CIN;
    #pragma unroll
    for (int i = t; i < CIN * 64; i += 256) {    // write: lanes vary c (coalesced)
        int s = i >> 5, c = i & 31;
        ob[s * CIN + c] = s_t[c * 65 + s];
    }
}

__device__ __forceinline__ u64 dup_f32x2(float v) {
    u64 r;
    asm("mov.b64 %0, {%1, %1};" : "=l"(r) : "f"(v));
    return r;
}

__global__ __launch_bounds__(THREADS) void dcn3d_kernel(
    const float* __restrict__ offs,
    const float* __restrict__ mask,
    const float* __restrict__ bias,
    float* __restrict__ out)
{
    __shared__ float s_val[POS * SVAL_STRIDE];   // [pos][cin], padded
    __shared__ float s_wp[8 * SWP_STRIDE];       // [ct][jj][cin][2], padded per ct

    const int t  = threadIdx.x;

    // GEMM mapping
    const int ct = t & 7;                        // co tile: co = ct*8 + 2jj + s
    const int pt = t >> 3;                       // pos pair: pos = pt*2 + p

    // Sampling mapping: two units per thread: (pos = t>>3 [+32], cq = t&7)
    const int cq    = t & 7;
    const int pos_a = t >> 3;                    // 0..31
    // unit B pos = pos_a + 32

    const int blkP = blockIdx.x * POS;
    const int b    = blkP / SPATIAL;             // whole block in one batch
    const int spb  = blkP - b * SPATIAL;

    const float* offb = offs + b * (2 * KTAPS * SPATIAL) + spb;
    const float* mb   = mask + b * (KTAPS * SPATIAL) + spb;
    const float* xTb  = g_xT + b * (SPATIAL * CIN);

    u64 acc[2][4];                               // [pos p][co-pair jj]
    #pragma unroll
    for (int p = 0; p < 2; p++)
        #pragma unroll
        for (int jj = 0; jj < 4; jj++) acc[p][jj] = 0ULL;

    for (int k = 0; k < KTAPS; k++) {
        const int kd = k / 9;
        const int kh = (k - kd * 9) / 3;
        const int kw = k - kd * 9 - kh * 3;

        __syncthreads();                         // prev GEMM reads done

        // stage interleaved weights for tap k: 2048 floats, strided dst
        {
            const float4* src = (const float4*)(g_wp + k * (COUT * CIN));
            #pragma unroll
            for (int r = 0; r < 2; r++) {
                int i = t + r * 256;             // float4 index 0..511
                int wct = i >> 6;                // 256 words per ct -> 64 float4
                int rem = i & 63;
                float4 v = src[i];
                *(float4*)(s_wp + wct * SWP_STRIDE + rem * 4) = v;
            }
        }

        // ---- sampling: 2 units (pos, cq) per thread ----
        #pragma unroll
        for (int u = 0; u < 2; u++) {
            const int posl = pos_a + u * 32;
            const int sp   = spb + posl;
            const int dout = sp / PLANE;
            const int r2   = sp - dout * PLANE;
            const int ho   = r2 / WDIM;
            const int wo   = r2 - ho * WDIM;

            const float oh = offb[(2 * k)     * SPATIAL + posl];
            const float ow = offb[(2 * k + 1) * SPATIAL + posl];
            const float m  = mb[k * SPATIAL + posl];

            const int  dp  = kd + dout - 1;
            const bool vdd = (dp >= 0) && (dp < DDIM);
            const int  di  = min(max(dp, 0), DDIM - 1);

            const float h = (float)(kh + ho - 1) + oh;
            const float w = (float)(kw + wo - 1) + ow;
            const float h0f = floorf(h), w0f = floorf(w);
            const float lh = h - h0f, lw = w - w0f;
            const int h0 = (int)h0f, w0 = (int)w0f;
            const int h1 = h0 + 1,   w1 = w0 + 1;

            const bool bh0 = (h0 >= 0) && (h0 < HDIM);
            const bool bh1 = (h1 >= 0) && (h1 < HDIM);
            const bool bw0 = (w0 >= 0) && (w0 < WDIM);
            const bool bw1 = (w1 >= 0) && (w1 < WDIM);

            const float w00 = (1.f - lh) * (1.f - lw) * ((bh0 && bw0 && vdd) ? m : 0.f);
            const float w01 = (1.f - lh) * lw         * ((bh0 && bw1 && vdd) ? m : 0.f);
            const float w10 = lh * (1.f - lw)         * ((bh1 && bw0 && vdd) ? m : 0.f);
            const float w11 = lh * lw                 * ((bh1 && bw1 && vdd) ? m : 0.f);

            const int hc0 = min(max(h0, 0), HDIM - 1);
            const int hc1 = min(max(h1, 0), HDIM - 1);
            const int wc0 = min(max(w0, 0), WDIM - 1);
            const int wc1 = min(max(w1, 0), WDIM - 1);

            const float* base = xTb + di * (PLANE * CIN) + cq * 4;
            const float4 c00 = *(const float4*)(base + (hc0 * WDIM + wc0) * CIN);
            const float4 c01 = *(const float4*)(base + (hc0 * WDIM + wc1) * CIN);
            const float4 c10 = *(const float4*)(base + (hc1 * WDIM + wc0) * CIN);
            const float4 c11 = *(const float4*)(base + (hc1 * WDIM + wc1) * CIN);

            float4 v;
            v.x = fmaf(w00, c00.x, fmaf(w01, c01.x, fmaf(w10, c10.x, w11 * c11.x)));
            v.y = fmaf(w00, c00.y, fmaf(w01, c01.y, fmaf(w10, c10.y, w11 * c11.y)));
            v.z = fmaf(w00, c00.z, fmaf(w01, c01.z, fmaf(w10, c10.z, w11 * c11.z)));
            v.w = fmaf(w00, c00.w, fmaf(w01, c01.w, fmaf(w10, c10.w, w11 * c11.w)));

            *(float4*)(s_val + posl * SVAL_STRIDE + cq * 4) = v;
        }

        __syncthreads();

        // ---- GEMM: acc[p][jj] += dup(sval[pos][c]) * wpair[jj][c] ----
        const int pos0 = pt * 2;
        #pragma unroll
        for (int q = 0; q < 8; q++) {            // cin quad
            const float4 a0 = *(const float4*)(s_val + pos0 * SVAL_STRIDE + q * 4);
            const float4 a1 = *(const float4*)(s_val + (pos0 + 1) * SVAL_STRIDE + q * 4);
            const float sv0[4] = {a0.x, a0.y, a0.z, a0.w};
            const float sv1[4] = {a1.x, a1.y, a1.z, a1.w};
            u64 d0[4], d1[4];
            #pragma unroll
            for (int c = 0; c < 4; c++) { d0[c] = dup_f32x2(sv0[c]); d1[c] = dup_f32x2(sv1[c]); }
            #pragma unroll
            for (int jj = 0; jj < 4; jj++) {
                const float* wb = s_wp + ct * SWP_STRIDE + jj * 64 + q * 8;
                const float4 wA = *(const float4*)(wb);       // pairs for cin q*4, q*4+1
                const float4 wB = *(const float4*)(wb + 4);   // pairs for cin q*4+2, q*4+3
                const u64 wp0 = ((const u64*)&wA)[0];
                const u64 wp1 = ((const u64*)&wA)[1];
                const u64 wp2 = ((const u64*)&wB)[0];
                const u64 wp3 = ((const u64*)&wB)[1];
                asm("fma.rn.f32x2 %0, %1, %2, %0;" : "+l"(acc[0][jj]) : "l"(d0[0]), "l"(wp0));
                asm("fma.rn.f32x2 %0, %1, %2, %0;" : "+l"(acc[0][jj]) : "l"(d0[1]), "l"(wp1));
                asm("fma.rn.f32x2 %0, %1, %2, %0;" : "+l"(acc[0][jj]) : "l"(d0[2]), "l"(wp2));
                asm("fma.rn.f32x2 %0, %1, %2, %0;" : "+l"(acc[0][jj]) : "l"(d0[3]), "l"(wp3));
                asm("fma.rn.f32x2 %0, %1, %2, %0;" : "+l"(acc[1][jj]) : "l"(d1[0]), "l"(wp0));
                asm("fma.rn.f32x2 %0, %1, %2, %0;" : "+l"(acc[1][jj]) : "l"(d1[1]), "l"(wp1));
                asm("fma.rn.f32x2 %0, %1, %2, %0;" : "+l"(acc[1][jj]) : "l"(d1[2]), "l"(wp2));
                asm("fma.rn.f32x2 %0, %1, %2, %0;" : "+l"(acc[1][jj]) : "l"(d1[3]), "l"(wp3));
            }
        }
    }

    // ---- epilogue: pos pair (pt*2, pt*2+1) x co (ct*8+2jj+s) ----
    const int sp0 = spb + pt * 2;
    float* ob = out + b * (COUT * SPATIAL) + sp0;
    #pragma unroll
    for (int jj = 0; jj < 4; jj++) {
        const int co0 = ct * 8 + 2 * jj;
        const float bv0 = __ldg(&bias[co0]);
        const float bv1 = __ldg(&bias[co0 + 1]);
        float p0c0, p0c1, p1c0, p1c1;
        asm("mov.b64 {%0, %1}, %2;" : "=f"(p0c0), "=f"(p0c1) : "l"(acc[0][jj]));
        asm("mov.b64 {%0, %1}, %2;" : "=f"(p1c0), "=f"(p1c1) : "l"(acc[1][jj]));
        float2 o0, o1;
        o0.x = p0c0 + bv0; o0.y = p1c0 + bv0;    // (pos0,pos1) for co0
        o1.x = p0c1 + bv1; o1.y = p1c1 + bv1;    // (pos0,pos1) for co1
        *(float2*)(ob + (u64)co0 * SPATIAL)       = o0;
        *(float2*)(ob + (u64)(co0 + 1) * SPATIAL) = o1;
    }
}

extern "C" void kernel_launch(void* const* d_in, const int* in_sizes, int n_in,
                              void* d_out, int out_size)
{
    const float* x    = (const float*)d_in[0];
    const float* offs = (const float*)d_in[1];
    const float* mask = (const float*)d_in[2];
    const float* w    = (const float*)d_in[3];
    const float* bias = (const float*)d_in[4];
    float* out = (float*)d_out;

    prep_w_kernel<<<(KTAPS * COUT * CIN + 255) / 256, 256>>>(w);
    prep_x_kernel<<<BATCH * (SPATIAL / 64), 256>>>(x);

    const int nblocks = (BATCH * SPATIAL) / POS;   // 576
    dcn3d_kernel<<<nblocks, THREADS>>>(offs, mask, bias, out);
}

// round 7
// speedup vs baseline: 1.2441x; 1.2441x over previous
#include <cuda_runtime.h>
#include <cstdint>

typedef unsigned long long u64;

// DeformConv3d: B=2, Cin=32, Cout=64, D=8, H=W=48, 3x3x3, s1, p1, d1.
#define CIN     32
#define COUT    64
#define DDIM    8
#define HDIM    48
#define WDIM    48
#define KTAPS   27
#define POSB    128                // positions per block
#define THREADS 128
#define PLANE   (HDIM * WDIM)      // 2304
#define SPATIAL (DDIM * PLANE)     // 18432
#define BATCH   2

#define WSTRIDE 68                 // words per cin row of staged weights
#define WTAP    (CIN * WSTRIDE)    // 2176 words per tap

// channels-last x: g_xT[b][sp][c]
__device__ float g_xT[BATCH * SPATIAL * CIN];
// pre-laid-out weights: per tap, word slot = cin*68 + ct*8 + (ct>>2)*4 + j  (co = ct*8+j)
__device__ float g_wp[KTAPS * WTAP];

__global__ void prep_w_kernel(const float* __restrict__ w) {
    int i = blockIdx.x * blockDim.x + threadIdx.x;
    if (i >= KTAPS * COUT * CIN) return;
    int k   = i / (COUT * CIN);
    int r   = i - k * (COUT * CIN);
    int co  = r >> 5;
    int cin = r & 31;
    int ct  = co >> 3;
    int j   = co & 7;
    int slot = cin * WSTRIDE + ct * 8 + (ct >> 2) * 4 + j;
    g_wp[k * WTAP + slot] = w[co * (CIN * KTAPS) + cin * KTAPS + k];
}

__global__ __launch_bounds__(256) void prep_x_kernel(const float* __restrict__ x) {
    __shared__ float s_t[CIN * 65];
    const int t   = threadIdx.x;
    const int blk = blockIdx.x;
    const int b   = blk / (SPATIAL / 64);
    const int sp0 = (blk - b * (SPATIAL / 64)) * 64;
    const float* xb = x + b * (CIN * SPATIAL);
    #pragma unroll
    for (int i = t; i < CIN * 64; i += 256) {
        int c = i >> 6, s = i & 63;
        s_t[c * 65 + s] = xb[c * SPATIAL + sp0 + s];
    }
    __syncthreads();
    float* ob = g_xT + (b * SPATIAL + sp0) * CIN;
    #pragma unroll
    for (int i = t; i < CIN * 64; i += 256) {
        int s = i >> 5, c = i & 31;
        ob[s * CIN + c] = s_t[c * 65 + s];
    }
}

__device__ __forceinline__ u64 dup_f32x2(float v) {
    u64 r;
    asm("mov.b64 %0, {%1, %1};" : "=l"(r) : "f"(v));
    return r;
}

__global__ __launch_bounds__(THREADS) void dcn3d_kernel(
    const float* __restrict__ offs,
    const float* __restrict__ mask,
    const float* __restrict__ bias,
    float* __restrict__ out)
{
    // s_val[cin][128 pos], pos-quad index XOR-swizzled by perm(cin)
    __shared__ float s_val[CIN * 128];
    __shared__ float s_w[WTAP];

    const int t  = threadIdx.x;
    const int cq = t & 7;            // sampling: channel quad
    const int pa = t >> 3;           // sampling: pos base (0..15), posl = pa + 16u
    const int ct = t & 7;            // GEMM: co tile (co = ct*8 + j)
    const int pt = t >> 3;           // GEMM: pos tile (pos = pt*8 + i)

    const int blkP = blockIdx.x * POSB;
    const int b    = blkP / SPATIAL;
    const int spb  = blkP - b * SPATIAL;

    const float* offb = offs + b * (2 * KTAPS * SPATIAL) + spb;
    const float* mb   = mask + b * (KTAPS * SPATIAL) + spb;
    const float* xTb  = g_xT + (size_t)b * (SPATIAL * CIN);

    // hoist per-unit spatial decomposition (posl fixed across taps)
    int dout_u[8], ho_u[8], wo_u[8];
    #pragma unroll
    for (int u = 0; u < 8; u++) {
        const int posl = pa + 16 * u;
        const int sp   = spb + posl;
        const int dd   = sp / PLANE;
        const int r2   = sp - dd * PLANE;
        dout_u[u] = dd;
        ho_u[u]   = r2 / WDIM;
        wo_u[u]   = r2 - (r2 / WDIM) * WDIM;
    }
    const int sq_base = pa >> 2;     // posl>>2 = sq_base + 4u
    const int sr      = pa & 3;      // posl&3

    u64 acc[8][4];                   // [co j][pos pair]
    #pragma unroll
    for (int j = 0; j < 8; j++)
        #pragma unroll
        for (int pp = 0; pp < 4; pp++) acc[j][pp] = 0ULL;

    const int Q0 = 2 * pt;
    const int Q1 = 2 * pt + 1;
    const int woff = ct * 8 + (ct >> 2) * 4;

    for (int k = 0; k < KTAPS; k++) {
        const int kd = k / 9;
        const int kh = (k - kd * 9) / 3;
        const int kw = k - kd * 9 - kh * 3;

        __syncthreads();             // previous tap's GEMM reads complete

        // ---- stage weights for tap k (contiguous copy) ----
        {
            const float4* src = (const float4*)(g_wp + k * WTAP);
            float4* dst = (float4*)s_w;
            #pragma unroll
            for (int i = t; i < WTAP / 4; i += THREADS) dst[i] = src[i];
        }

        // ---- sampling: 8 units of (pos, cq) per thread ----
        #pragma unroll
        for (int u = 0; u < 8; u++) {
            const int posl = pa + 16 * u;
            const int dout = dout_u[u];
            const int ho   = ho_u[u];
            const int wo   = wo_u[u];

            const float oh = offb[(2 * k)     * SPATIAL + posl];
            const float ow = offb[(2 * k + 1) * SPATIAL + posl];
            const float m  = mb[k * SPATIAL + posl];

            const int  dp  = kd + dout - 1;
            const bool vdd = (dp >= 0) && (dp < DDIM);
            const int  di  = min(max(dp, 0), DDIM - 1);

            const float h = (float)(kh + ho - 1) + oh;
            const float w = (float)(kw + wo - 1) + ow;
            const float h0f = floorf(h), w0f = floorf(w);
            const float lh = h - h0f, lw = w - w0f;
            const int h0 = (int)h0f, w0 = (int)w0f;
            const int h1 = h0 + 1,   w1 = w0 + 1;

            const bool bh0 = (h0 >= 0) && (h0 < HDIM);
            const bool bh1 = (h1 >= 0) && (h1 < HDIM);
            const bool bw0 = (w0 >= 0) && (w0 < WDIM);
            const bool bw1 = (w1 >= 0) && (w1 < WDIM);

            const float w00 = (1.f - lh) * (1.f - lw) * ((bh0 && bw0 && vdd) ? m : 0.f);
            const float w01 = (1.f - lh) * lw         * ((bh0 && bw1 && vdd) ? m : 0.f);
            const float w10 = lh * (1.f - lw)         * ((bh1 && bw0 && vdd) ? m : 0.f);
            const float w11 = lh * lw                 * ((bh1 && bw1 && vdd) ? m : 0.f);

            const int hc0 = min(max(h0, 0), HDIM - 1);
            const int hc1 = min(max(h1, 0), HDIM - 1);
            const int wc0 = min(max(w0, 0), WDIM - 1);
            const int wc1 = min(max(w1, 0), WDIM - 1);

            const float* base = xTb + (size_t)di * (PLANE * CIN) + cq * 4;
            const float4 c00 = *(const float4*)(base + (size_t)(hc0 * WDIM + wc0) * CIN);
            const float4 c01 = *(const float4*)(base + (size_t)(hc0 * WDIM + wc1) * CIN);
            const float4 c10 = *(const float4*)(base + (size_t)(hc1 * WDIM + wc0) * CIN);
            const float4 c11 = *(const float4*)(base + (size_t)(hc1 * WDIM + wc1) * CIN);

            float4 v;
            v.x = fmaf(w00, c00.x, fmaf(w01, c01.x, fmaf(w10, c10.x, w11 * c11.x)));
            v.y = fmaf(w00, c00.y, fmaf(w01, c01.y, fmaf(w10, c10.y, w11 * c11.y)));
            v.z = fmaf(w00, c00.z, fmaf(w01, c01.z, fmaf(w10, c10.z, w11 * c11.z)));
            v.w = fmaf(w00, c00.w, fmaf(w01, c01.w, fmaf(w10, c10.w, w11 * c11.w)));

            // swizzled scatter: cin = cq*4 + c, perm(cin) = (c<<3)|cq
            const int sq = sq_base + 4 * u;
            const float vv[4] = {v.x, v.y, v.z, v.w};
            #pragma unroll
            for (int c = 0; c < 4; c++) {
                const int cin  = cq * 4 + c;
                const int perm = (c << 3) | cq;
                s_val[cin * 128 + ((sq ^ perm) << 2) + sr] = vv[c];
            }
        }

        __syncthreads();

        // ---- GEMM: 8 pos x 8 co per thread, f32x2 over pos pairs ----
        #pragma unroll
        for (int cin = 0; cin < CIN; cin++) {
            const int perm = ((cin & 3) << 3) | (cin >> 2);
            const float4 a0 = *(const float4*)(s_val + cin * 128 + ((Q0 ^ perm) << 2));
            const float4 a1 = *(const float4*)(s_val + cin * 128 + ((Q1 ^ perm) << 2));
            const u64 p0 = ((const u64*)&a0)[0];   // (pos 8pt+0, +1)
            const u64 p1 = ((const u64*)&a0)[1];   // (+2, +3)
            const u64 p2 = ((const u64*)&a1)[0];   // (+4, +5)
            const u64 p3 = ((const u64*)&a1)[1];   // (+6, +7)
            const float4 wq0 = *(const float4*)(s_w + cin * WSTRIDE + woff);
            const float4 wq1 = *(const float4*)(s_w + cin * WSTRIDE + woff + 4);
            const float wj[8] = {wq0.x, wq0.y, wq0.z, wq0.w,
                                 wq1.x, wq1.y, wq1.z, wq1.w};
            #pragma unroll
            for (int j = 0; j < 8; j++) {
                const u64 wd = dup_f32x2(wj[j]);
                asm("fma.rn.f32x2 %0, %1, %2, %0;" : "+l"(acc[j][0]) : "l"(p0), "l"(wd));
                asm("fma.rn.f32x2 %0, %1, %2, %0;" : "+l"(acc[j][1]) : "l"(p1), "l"(wd));
                asm("fma.rn.f32x2 %0, %1, %2, %0;" : "+l"(acc[j][2]) : "l"(p2), "l"(wd));
                asm("fma.rn.f32x2 %0, %1, %2, %0;" : "+l"(acc[j][3]) : "l"(p3), "l"(wd));
            }
        }
    }

    // ---- epilogue: pos [spb+pt*8, +8), co [ct*8, +8) ----
    float* ob = out + (size_t)b * (COUT * SPATIAL) + spb + pt * 8;
    #pragma unroll
    for (int j = 0; j < 8; j++) {
        const int co = ct * 8 + j;
        const float bv = __ldg(&bias[co]);
        float f[8];
        #pragma unroll
        for (int pp = 0; pp < 4; pp++) {
            asm("mov.b64 {%0, %1}, %2;"
                : "=f"(f[2 * pp]), "=f"(f[2 * pp + 1]) : "l"(acc[j][pp]));
        }
        float4 o0, o1;
        o0.x = f[0] + bv; o0.y = f[1] + bv; o0.z = f[2] + bv; o0.w = f[3] + bv;
        o1.x = f[4] + bv; o1.y = f[5] + bv; o1.z = f[6] + bv; o1.w = f[7] + bv;
        *(float4*)(ob + (size_t)co * SPATIAL)     = o0;
        *(float4*)(ob + (size_t)co * SPATIAL + 4) = o1;
    }
}

extern "C" void kernel_launch(void* const* d_in, const int* in_sizes, int n_in,
                              void* d_out, int out_size)
{
    const float* x    = (const float*)d_in[0];
    const float* offs = (const float*)d_in[1];
    const float* mask = (const float*)d_in[2];
    const float* w    = (const float*)d_in[3];
    const float* bias = (const float*)d_in[4];
    float* out = (float*)d_out;

    prep_w_kernel<<<(KTAPS * COUT * CIN + 255) / 256, 256>>>(w);
    prep_x_kernel<<<BATCH * (SPATIAL / 64), 256>>>(x);

    const int nblocks = (BATCH * SPATIAL) / POSB;   // 288
    dcn3d_kernel<<<nblocks, THREADS>>>(offs, mask, bias, out);
}

// round 8
// speedup vs baseline: 1.2974x; 1.0428x over previous
#include <cuda_runtime.h>
#include <cstdint>

typedef unsigned long long u64;

// DeformConv3d: B=2, Cin=32, Cout=64, D=8, H=W=48, 3x3x3, s1, p1, d1.
#define CIN     32
#define COUT    64
#define DDIM    8
#define HDIM    48
#define WDIM    48
#define KTAPS   27
#define POSB    128                // positions per block
#define THREADS 256                // 128 consumers + 128 producers
#define PLANE   (HDIM * WDIM)      // 2304
#define SPATIAL (DDIM * PLANE)     // 18432
#define BATCH   2

#define WTAP    (CIN * COUT)       // 2048 words per tap

// channels-last x: g_xT[b][sp][c]
__device__ float g_xT[BATCH * SPATIAL * CIN];
// weights: g_wp[k][cin][co]
__device__ float g_wp[KTAPS * WTAP];

#define BAR_SYNC(id)   asm volatile("bar.sync %0, 256;"   :: "r"(id) : "memory")
#define BAR_ARRIVE(id) asm volatile("bar.arrive %0, 256;" :: "r"(id) : "memory")

// ---- merged prep: blocks [0,576) transpose x; blocks [576, 576+216) lay out w ----
__global__ __launch_bounds__(256) void prep_kernel(const float* __restrict__ x,
                                                   const float* __restrict__ w) {
    const int t = threadIdx.x;
    if (blockIdx.x < BATCH * (SPATIAL / 64)) {
        __shared__ float s_t[CIN * 65];
        const int blk = blockIdx.x;
        const int b   = blk / (SPATIAL / 64);
        const int sp0 = (blk - b * (SPATIAL / 64)) * 64;
        const float* xb = x + b * (CIN * SPATIAL);
        #pragma unroll
        for (int i = t; i < CIN * 64; i += 256) {
            int c = i >> 6, s = i & 63;
            s_t[c * 65 + s] = xb[c * SPATIAL + sp0 + s];
        }
        __syncthreads();
        float* ob = g_xT + (b * SPATIAL + sp0) * CIN;
        #pragma unroll
        for (int i = t; i < CIN * 64; i += 256) {
            int s = i >> 5, c = i & 31;
            ob[s * CIN + c] = s_t[c * 65 + s];
        }
    } else {
        int i = (blockIdx.x - BATCH * (SPATIAL / 64)) * 256 + t;
        if (i < KTAPS * WTAP) {
            int k   = i / WTAP;
            int r   = i - k * WTAP;
            int cin = r >> 6;
            int co  = r & 63;
            g_wp[i] = w[co * (CIN * KTAPS) + cin * KTAPS + k];
        }
    }
}

__device__ __forceinline__ u64 dup_f32x2(float v) {
    u64 r;
    asm("mov.b64 %0, {%1, %1};" : "=l"(r) : "f"(v));
    return r;
}

__global__ __launch_bounds__(THREADS, 2) void dcn3d_kernel(
    const float* __restrict__ offs,
    const float* __restrict__ mask,
    const float* __restrict__ bias,
    float* __restrict__ out)
{
    // double-buffered sampled values: [buf][cin][128 pos] (pos-quad XOR swizzle)
    __shared__ float s_val[2][CIN * 128];

    const int t = threadIdx.x;

    const int blkP = blockIdx.x * POSB;
    const int b    = blkP / SPATIAL;
    const int spb  = blkP - b * SPATIAL;

    if (t >= 128) {
        // =================== PRODUCER warps (sampling) ===================
        const int tp = t - 128;
        const int cq = tp & 7;           // channel quad
        const int pa = tp >> 3;          // pos base (0..15), posl = pa + 16u

        const float* offb = offs + b * (2 * KTAPS * SPATIAL) + spb;
        const float* mb   = mask + b * (KTAPS * SPATIAL) + spb;
        const float* xTb  = g_xT + (size_t)b * (SPATIAL * CIN);

        int dout_u[8], ho_u[8], wo_u[8];
        #pragma unroll
        for (int u = 0; u < 8; u++) {
            const int posl = pa + 16 * u;
            const int sp   = spb + posl;
            const int dd   = sp / PLANE;
            const int r2   = sp - dd * PLANE;
            dout_u[u] = dd;
            ho_u[u]   = r2 / WDIM;
            wo_u[u]   = r2 - (r2 / WDIM) * WDIM;
        }
        const int sq_base = pa >> 2;
        const int sr      = pa & 3;

        for (int k = 0; k < KTAPS; k++) {
            const int kd = k / 9;
            const int kh = (k - kd * 9) / 3;
            const int kw = k - kd * 9 - kh * 3;
            const int buf = k & 1;

            if (k >= 2) BAR_SYNC(3 + buf);      // wait buffer empty

            float* sv = s_val[buf];

            #pragma unroll
            for (int u = 0; u < 8; u++) {
                const int posl = pa + 16 * u;
                const int dout = dout_u[u];
                const int ho   = ho_u[u];
                const int wo   = wo_u[u];

                const float oh = offb[(2 * k)     * SPATIAL + posl];
                const float ow = offb[(2 * k + 1) * SPATIAL + posl];
                const float m  = mb[k * SPATIAL + posl];

                const int  dp  = kd + dout - 1;
                const bool vdd = (dp >= 0) && (dp < DDIM);
                const int  di  = min(max(dp, 0), DDIM - 1);

                const float h = (float)(kh + ho - 1) + oh;
                const float w = (float)(kw + wo - 1) + ow;
                const float h0f = floorf(h), w0f = floorf(w);
                const float lh = h - h0f, lw = w - w0f;
                const int h0 = (int)h0f, w0 = (int)w0f;
                const int h1 = h0 + 1,   w1 = w0 + 1;

                const bool bh0 = (h0 >= 0) && (h0 < HDIM);
                const bool bh1 = (h1 >= 0) && (h1 < HDIM);
                const bool bw0 = (w0 >= 0) && (w0 < WDIM);
                const bool bw1 = (w1 >= 0) && (w1 < WDIM);

                const float w00 = (1.f - lh) * (1.f - lw) * ((bh0 && bw0 && vdd) ? m : 0.f);
                const float w01 = (1.f - lh) * lw         * ((bh0 && bw1 && vdd) ? m : 0.f);
                const float w10 = lh * (1.f - lw)         * ((bh1 && bw0 && vdd) ? m : 0.f);
                const float w11 = lh * lw                 * ((bh1 && bw1 && vdd) ? m : 0.f);

                const int hc0 = min(max(h0, 0), HDIM - 1);
                const int hc1 = min(max(h1, 0), HDIM - 1);
                const int wc0 = min(max(w0, 0), WDIM - 1);
                const int wc1 = min(max(w1, 0), WDIM - 1);

                const float* base = xTb + (size_t)di * (PLANE * CIN) + cq * 4;
                const float4 c00 = *(const float4*)(base + (size_t)(hc0 * WDIM + wc0) * CIN);
                const float4 c01 = *(const float4*)(base + (size_t)(hc0 * WDIM + wc1) * CIN);
                const float4 c10 = *(const float4*)(base + (size_t)(hc1 * WDIM + wc0) * CIN);
                const float4 c11 = *(const float4*)(base + (size_t)(hc1 * WDIM + wc1) * CIN);

                float4 v;
                v.x = fmaf(w00, c00.x, fmaf(w01, c01.x, fmaf(w10, c10.x, w11 * c11.x)));
                v.y = fmaf(w00, c00.y, fmaf(w01, c01.y, fmaf(w10, c10.y, w11 * c11.y)));
                v.z = fmaf(w00, c00.z, fmaf(w01, c01.z, fmaf(w10, c10.z, w11 * c11.z)));
                v.w = fmaf(w00, c00.w, fmaf(w01, c01.w, fmaf(w10, c10.w, w11 * c11.w)));

                // swizzled scatter: cin = cq*4 + c, perm(cin) = (c<<3)|cq
                const int sq = sq_base + 4 * u;
                const float vv[4] = {v.x, v.y, v.z, v.w};
                #pragma unroll
                for (int c = 0; c < 4; c++) {
                    const int perm = (c << 3) | cq;
                    sv[(cq * 4 + c) * 128 + ((sq ^ perm) << 2) + sr] = vv[c];
                }
            }

            asm volatile("membar.cta;" ::: "memory");   // make STS visible
            BAR_ARRIVE(1 + buf);                        // signal buffer full
        }
    } else {
        // =================== CONSUMER warps (GEMM) ===================
        const int ct = t & 7;            // co tile (co = ct*8 + j)
        const int pt = t >> 3;           // pos tile (pos = pt*8 + i)
        const int Q0 = 2 * pt;
        const int Q1 = 2 * pt + 1;

        u64 acc[8][4];
        #pragma unroll
        for (int j = 0; j < 8; j++)
            #pragma unroll
            for (int pp = 0; pp < 4; pp++) acc[j][pp] = 0ULL;

        for (int k = 0; k < KTAPS; k++) {
            const int buf = k & 1;
            BAR_SYNC(1 + buf);                          // wait buffer full

            const float* sv = s_val[buf];
            const float* wt = g_wp + k * WTAP + ct * 8;

            #pragma unroll
            for (int cin = 0; cin < CIN; cin++) {
                const int perm = ((cin & 3) << 3) | (cin >> 2);
                const float4 a0 = *(const float4*)(sv + cin * 128 + ((Q0 ^ perm) << 2));
                const float4 a1 = *(const float4*)(sv + cin * 128 + ((Q1 ^ perm) << 2));
                const u64 p0 = ((const u64*)&a0)[0];
                const u64 p1 = ((const u64*)&a0)[1];
                const u64 p2 = ((const u64*)&a1)[0];
                const u64 p3 = ((const u64*)&a1)[1];
                const float4 wq0 = __ldg((const float4*)(wt + cin * COUT));
                const float4 wq1 = __ldg((const float4*)(wt + cin * COUT + 4));
                const float wj[8] = {wq0.x, wq0.y, wq0.z, wq0.w,
                                     wq1.x, wq1.y, wq1.z, wq1.w};
                #pragma unroll
                for (int j = 0; j < 8; j++) {
                    const u64 wd = dup_f32x2(wj[j]);
                    asm("fma.rn.f32x2 %0, %1, %2, %0;" : "+l"(acc[j][0]) : "l"(p0), "l"(wd));
                    asm("fma.rn.f32x2 %0, %1, %2, %0;" : "+l"(acc[j][1]) : "l"(p1), "l"(wd));
                    asm("fma.rn.f32x2 %0, %1, %2, %0;" : "+l"(acc[j][2]) : "l"(p2), "l"(wd));
                    asm("fma.rn.f32x2 %0, %1, %2, %0;" : "+l"(acc[j][3]) : "l"(p3), "l"(wd));
                }
            }

            BAR_ARRIVE(3 + buf);                        // signal buffer empty
        }

        // ---- epilogue: pos [spb+pt*8, +8), co [ct*8, +8) ----
        float* ob = out + (size_t)b * (COUT * SPATIAL) + spb + pt * 8;
        #pragma unroll
        for (int j = 0; j < 8; j++) {
            const int co = ct * 8 + j;
            const float bv = __ldg(&bias[co]);
            float f[8];
            #pragma unroll
            for (int pp = 0; pp < 4; pp++) {
                asm("mov.b64 {%0, %1}, %2;"
                    : "=f"(f[2 * pp]), "=f"(f[2 * pp + 1]) : "l"(acc[j][pp]));
            }
            float4 o0, o1;
            o0.x = f[0] + bv; o0.y = f[1] + bv; o0.z = f[2] + bv; o0.w = f[3] + bv;
            o1.x = f[4] + bv; o1.y = f[5] + bv; o1.z = f[6] + bv; o1.w = f[7] + bv;
            *(float4*)(ob + (size_t)co * SPATIAL)     = o0;
            *(float4*)(ob + (size_t)co * SPATIAL + 4) = o1;
        }
    }
}

extern "C" void kernel_launch(void* const* d_in, const int* in_sizes, int n_in,
                              void* d_out, int out_size)
{
    const float* x    = (const float*)d_in[0];
    const float* offs = (const float*)d_in[1];
    const float* mask = (const float*)d_in[2];
    const float* w    = (const float*)d_in[3];
    const float* bias = (const float*)d_in[4];
    float* out = (float*)d_out;

    const int nprep = BATCH * (SPATIAL / 64) + (KTAPS * WTAP + 255) / 256;  // 576 + 216
    prep_kernel<<<nprep, 256>>>(x, w);

    const int nblocks = (BATCH * SPATIAL) / POSB;   // 288
    dcn3d_kernel<<<nblocks, THREADS>>>(offs, mask, bias, out);
}